// round 13
// baseline (speedup 1.0000x reference)
#include <cuda_runtime.h>
#include <cuda_bf16.h>

// ONE kernel, ZERO inter-block sync. n=1024, K=8 -> 8192 entries.
//   total = sum_{a in pos, b in neg} log(1 + exp(v_b - v_a)) / (P*N)
//
// Tile decomposition: entries split into RNG=34 ranges (241 each). Block
// b=(i,j) locally compacts positives of range i and negatives of range j
// into SMEM (ballot + smem atomic), then computes its pos-tile x neg-tile
// pairs from SMEM. Union over 1156 blocks covers every cross pair exactly
// once -> no grid barrier, no multi-kernel graph.
// 8 CTAs/SM co-resident (128 thr x 64 regs x 8 = full RF): eight independent
// per-block critical paths interleave on each SM.
//
// Pair math (validated rel_err ~1e-7):
//   exp(q-p) = exp(q)*exp(-p);  sum log(1+t) = (sum log2 prod(t/64)+corr)*ln2
//   fma.rn.f32x2 / mul.rn.f32x2 packed: 1 instruction covers 2 pairs.
// Zero-padded SMEM slots give t' = 1/64 whose log2 exactly cancels the +6
// per-pair correction.

#define RNG    34
#define RSZ    241            // 34*241 = 8194 >= 8192
#define GRID   (RNG * RNG)    // 1156 <= 148*8 = 1184 (one wave)
#define TPB    128
#define WARPS  (TPB / 32)
#define LCAP   256            // smem list capacity (>= 241+pad, /16 aligned)
#define NSLOT  16

__device__ unsigned int g_P;        // global positive count   (reset per call)
__device__ unsigned int g_N;        // global negative count   (reset per call)
__device__ unsigned int g_done;     // finished blocks         (reset per call)
__device__ double g_accSlot[NSLOT];

typedef unsigned long long u64;

__device__ __forceinline__ u64 pk2(float lo, float hi) {
    u64 r; asm("mov.b64 %0, {%1, %2};" : "=l"(r) : "f"(lo), "f"(hi)); return r;
}
__device__ __forceinline__ void upk2(u64 v, float& lo, float& hi) {
    asm("mov.b64 {%0, %1}, %2;" : "=f"(lo), "=f"(hi) : "l"(v));
}
__device__ __forceinline__ u64 fma2(u64 a, u64 b, u64 c) {
    u64 d; asm("fma.rn.f32x2 %0, %1, %2, %3;" : "=l"(d) : "l"(a), "l"(b), "l"(c));
    return d;
}
__device__ __forceinline__ u64 mul2(u64 a, u64 b) {
    u64 d; asm("mul.rn.f32x2 %0, %1, %2;" : "=l"(d) : "l"(a), "l"(b));
    return d;
}

// Product over one negative float4 of t' = (q*F + 1)/64, for 2 packed positives.
__device__ __forceinline__ u64 tprod4(u64 qx, u64 qy, u64 qz, u64 qw,
                                      u64 Fs, u64 S2) {
    u64 t0 = fma2(qx, Fs, S2);
    u64 t1 = fma2(qy, Fs, S2);
    u64 t2 = fma2(qz, Fs, S2);
    u64 t3 = fma2(qw, Fs, S2);
    return mul2(mul2(t0, t1), mul2(t2, t3));
}

__global__ void __launch_bounds__(TPB, 8)
rul_tile_kernel(const float* __restrict__ pred,
                const int* __restrict__ label,
                int total,
                float* __restrict__ out) {
    __shared__ __align__(16) float sPos[LCAP];   // exp(-v) list, zero padded
    __shared__ __align__(16) float sNeg[LCAP];   // exp(+v) list, zero padded
    __shared__ unsigned int sCntP, sCntN;
    __shared__ float sRed[WARPS];

    const unsigned lane = threadIdx.x & 31u;
    const unsigned warp = threadIdx.x >> 5;
    const unsigned ltmask = (1u << lane) - 1u;
    const int pi = blockIdx.x / RNG;     // positive range index
    const int nj = blockIdx.x % RNG;     // negative range index

    // ---- zero lists + counters ---------------------------------------------
    for (int k = (int)threadIdx.x; k < LCAP; k += TPB) {
        sPos[k] = 0.0f; sNeg[k] = 0.0f;
    }
    if (threadIdx.x == 0) { sCntP = 0u; sCntN = 0u; }
    __syncthreads();

    // ---- local compaction (strided passes over the range) -------------------
    for (int base = 0; base < RSZ; base += TPB) {
        int idx = base + (int)threadIdx.x;
        int ip = pi * RSZ + idx;
        int in = nj * RSZ + idx;
        bool inRp = (idx < RSZ) && (ip < total);
        bool inRn = (idx < RSZ) && (in < total);
        float vp = 0.0f, vn = 0.0f;
        int yp = -1, yn = -1;
        if (inRp) { vp = pred[ip]; yp = label[ip]; }
        if (inRn) { vn = pred[in]; yn = label[in]; }
        bool isPos = inRp && (yp == 1);
        bool isNeg = inRn && (yn == 0);

        unsigned mp = __ballot_sync(0xFFFFFFFFu, isPos);
        unsigned mn = __ballot_sync(0xFFFFFFFFu, isNeg);
        unsigned bp = 0, bn = 0;
        if (lane == 0) {
            if (mp) bp = atomicAdd(&sCntP, (unsigned)__popc(mp));
            if (mn) bn = atomicAdd(&sCntN, (unsigned)__popc(mn));
        }
        bp = __shfl_sync(0xFFFFFFFFu, bp, 0);
        bn = __shfl_sync(0xFFFFFFFFu, bn, 0);
        if (isPos) sPos[bp + __popc(mp & ltmask)] = __expf(-vp);
        if (isNeg) sNeg[bn + __popc(mn & ltmask)] = __expf(vn);
    }
    __syncthreads();

    const int cntP = (int)sCntP;
    const int cntN = (int)sCntN;

    // Contribute local counts to global P,N (each range counted once).
    if (threadIdx.x == 0) {
        if (nj == 0 && cntP) atomicAdd(&g_P, (unsigned)cntP);
        if (pi == 0 && cntN) atomicAdd(&g_N, (unsigned)cntN);
    }

    // ---- pair phase from SMEM ------------------------------------------------
    int G8 = (cntP + 7) >> 3;                 // pos groups of 8
    int nChunk = (cntN + 15) >> 4;            // neg chunks of 16
    const int units = G8 * nChunk;            // ~120 typical (<= TPB)

    const float4* __restrict__ posf4 = reinterpret_cast<const float4*>(sPos);
    const float4* __restrict__ negf4 = reinterpret_cast<const float4*>(sNeg);
    const u64 S2 = pk2(0.015625f, 0.015625f); // 1/64

    float lgSum = 0.0f;
    int   nUnits = 0;
    for (int u = (int)threadIdx.x; u < units; u += TPB) {
        int chunk = u / G8;                   // consecutive threads share chunk
        int pg    = u - chunk * G8;

        float4 Fa = posf4[2 * pg];
        float4 Fb = posf4[2 * pg + 1];
        u64 Fs0 = mul2(pk2(Fa.x, Fa.y), S2);
        u64 Fs1 = mul2(pk2(Fa.z, Fa.w), S2);
        u64 Fs2 = mul2(pk2(Fb.x, Fb.y), S2);
        u64 Fs3 = mul2(pk2(Fb.z, Fb.w), S2);

        const float4* qp = negf4 + chunk * 4;
        u64 m0 = 0, m1 = 0, m2 = 0, m3 = 0;
#pragma unroll
        for (int k = 0; k < 4; ++k) {
            float4 q = qp[k];
            u64 qx = pk2(q.x, q.x), qy = pk2(q.y, q.y);
            u64 qz = pk2(q.z, q.z), qw = pk2(q.w, q.w);
            u64 p0 = tprod4(qx, qy, qz, qw, Fs0, S2);
            u64 p1 = tprod4(qx, qy, qz, qw, Fs1, S2);
            u64 p2 = tprod4(qx, qy, qz, qw, Fs2, S2);
            u64 p3 = tprod4(qx, qy, qz, qw, Fs3, S2);
            if (k == 0) { m0 = p0; m1 = p1; m2 = p2; m3 = p3; }
            else {
                m0 = mul2(m0, p0); m1 = mul2(m1, p1);
                m2 = mul2(m2, p2); m3 = mul2(m3, p3);
            }
        }
        float a, b;
        upk2(m0, a, b); lgSum += __log2f(a) + __log2f(b);
        upk2(m1, a, b); lgSum += __log2f(a) + __log2f(b);
        upk2(m2, a, b); lgSum += __log2f(a) + __log2f(b);
        upk2(m3, a, b); lgSum += __log2f(a) + __log2f(b);
        ++nUnits;
    }
    // +16*log2(64) = 96 per scalar chain (8 chains/unit); pads cancel exactly.
    float threadSum = (lgSum + 768.0f * (float)nUnits) * 0.6931471805599453f;

    // ---- block reduction ------------------------------------------------------
#pragma unroll
    for (int off = 16; off > 0; off >>= 1)
        threadSum += __shfl_down_sync(0xFFFFFFFFu, threadSum, off);
    if (lane == 0) sRed[warp] = threadSum;
    __syncthreads();
    if (warp == 0) {
        float s = (lane < WARPS) ? sRed[lane] : 0.0f;
#pragma unroll
        for (int off = 16; off > 0; off >>= 1)
            s += __shfl_down_sync(0xFFFFFFFFu, s, off);

        // ---- slotted accumulate + last-block finalize --------------------------
        if (lane == 0) {
            atomicAdd(&g_accSlot[blockIdx.x & (NSLOT - 1)], (double)s);
            __threadfence();
            unsigned int d = atomicAdd(&g_done, 1u);
            if (d == GRID - 1) {
                __threadfence();
                double acc = 0.0;
#pragma unroll
                for (int k = 0; k < NSLOT; ++k) {
                    acc += *(volatile double*)&g_accSlot[k];
                    g_accSlot[k] = 0.0;
                }
                double P = (double)*(volatile unsigned int*)&g_P;
                double N = (double)*(volatile unsigned int*)&g_N;
                out[0] = (float)(acc / (P * N));
                g_P = 0u;
                g_N = 0u;
                g_done = 0u;
            }
        }
    }
}

// ---------------------------------------------------------------------------
extern "C" void kernel_launch(void* const* d_in, const int* in_sizes, int n_in,
                              void* d_out, int out_size) {
    const float* pred  = (const float*)d_in[0];
    const int*   label = (const int*)d_in[1];
    int total = in_sizes[0];   // n*K = 8192

    rul_tile_kernel<<<GRID, TPB>>>(pred, label, total, (float*)d_out);
}

// round 14
// speedup vs baseline: 1.1875x; 1.1875x over previous
#include <cuda_runtime.h>
#include <cuda_bf16.h>

// ONE kernel, ZERO inter-block sync. n=1024, K=8 -> 8192 entries.
//   total = sum_{a in pos, b in neg} log(1 + exp(v_b - v_a)) / (P*N)
//
// Tile decomposition: entries split into RNG=24 ranges (342 each). Block
// b=(i,j) locally compacts positives of range i and negatives of range j
// into SMEM (ballot + smem atomic), then computes its pos-tile x neg-tile
// pairs from SMEM. Union over 576 blocks covers every cross pair exactly
// once -> no grid barrier, no multi-kernel graph. 4 CTAs/SM co-resident.
//
// Pair math (validated rel_err ~1e-7):
//   exp(q-p) = exp(q)*exp(-p);  sum log(1+t) = (sum log2 prod(t/64)+corr)*ln2
//   fma.rn.f32x2 / mul.rn.f32x2 packed: 1 instruction covers 2 pairs.
// NEW: positives are lane-broadcast (pk2(F,F), once per unit); negatives are
// consumed directly as u64 lane-pairs via ulonglong2 smem loads -> zero
// per-negative pack instructions in the inner loop.
// Zero-padded SMEM slots give t' = 1/64 whose log2 exactly cancels the +6
// per-pair correction.

#define RNG    24
#define RSZ    342            // 24*342 = 8208 >= 8192
#define GRID   (RNG * RNG)    // 576
#define TPB    256
#define WARPS  (TPB / 32)
#define LCAP   352            // smem list capacity (>= 342+pad, /32 elems)
#define NSLOT  16

__device__ unsigned int g_P;        // global positive count   (reset per call)
__device__ unsigned int g_N;        // global negative count   (reset per call)
__device__ unsigned int g_done;     // finished blocks         (reset per call)
__device__ double g_accSlot[NSLOT];

typedef unsigned long long u64;

__device__ __forceinline__ u64 pk2(float lo, float hi) {
    u64 r; asm("mov.b64 %0, {%1, %2};" : "=l"(r) : "f"(lo), "f"(hi)); return r;
}
__device__ __forceinline__ void upk2(u64 v, float& lo, float& hi) {
    asm("mov.b64 {%0, %1}, %2;" : "=f"(lo), "=f"(hi) : "l"(v));
}
__device__ __forceinline__ u64 fma2(u64 a, u64 b, u64 c) {
    u64 d; asm("fma.rn.f32x2 %0, %1, %2, %3;" : "=l"(d) : "l"(a), "l"(b), "l"(c));
    return d;
}
__device__ __forceinline__ u64 mul2(u64 a, u64 b) {
    u64 d; asm("mul.rn.f32x2 %0, %1, %2;" : "=l"(d) : "l"(a), "l"(b));
    return d;
}

__global__ void __launch_bounds__(TPB, 4)
rul_tile_kernel(const float* __restrict__ pred,
                const int* __restrict__ label,
                int total,
                float* __restrict__ out) {
    __shared__ __align__(16) float sPos[LCAP];   // exp(-v) list, zero padded
    __shared__ __align__(16) float sNeg[LCAP];   // exp(+v) list, zero padded
    __shared__ unsigned int sCntP, sCntN;
    __shared__ float sRed[WARPS];

    const unsigned lane = threadIdx.x & 31u;
    const unsigned warp = threadIdx.x >> 5;
    const unsigned ltmask = (1u << lane) - 1u;
    const int pi = blockIdx.x / RNG;     // positive range index
    const int nj = blockIdx.x % RNG;     // negative range index

    // ---- zero lists + counters ---------------------------------------------
    for (int k = (int)threadIdx.x; k < LCAP; k += TPB) {
        sPos[k] = 0.0f; sNeg[k] = 0.0f;
    }
    if (threadIdx.x == 0) { sCntP = 0u; sCntN = 0u; }
    __syncthreads();

    // ---- local compaction (strided passes over the range) -------------------
    for (int base = 0; base < RSZ; base += TPB) {
        int idx = base + (int)threadIdx.x;
        int ip = pi * RSZ + idx;
        int in = nj * RSZ + idx;
        bool inRp = (idx < RSZ) && (ip < total);
        bool inRn = (idx < RSZ) && (in < total);
        float vp = 0.0f, vn = 0.0f;
        int yp = -1, yn = -1;
        if (inRp) { vp = pred[ip]; yp = label[ip]; }
        if (inRn) { vn = pred[in]; yn = label[in]; }
        bool isPos = inRp && (yp == 1);
        bool isNeg = inRn && (yn == 0);

        unsigned mp = __ballot_sync(0xFFFFFFFFu, isPos);
        unsigned mn = __ballot_sync(0xFFFFFFFFu, isNeg);
        unsigned bp = 0, bn = 0;
        if (lane == 0) {
            if (mp) bp = atomicAdd(&sCntP, (unsigned)__popc(mp));
            if (mn) bn = atomicAdd(&sCntN, (unsigned)__popc(mn));
        }
        bp = __shfl_sync(0xFFFFFFFFu, bp, 0);
        bn = __shfl_sync(0xFFFFFFFFu, bn, 0);
        if (isPos) sPos[bp + __popc(mp & ltmask)] = __expf(-vp);
        if (isNeg) sNeg[bn + __popc(mn & ltmask)] = __expf(vn);
    }
    __syncthreads();

    const int cntP = (int)sCntP;
    const int cntN = (int)sCntN;

    // Contribute local counts to global P,N (each range counted once).
    if (threadIdx.x == 0) {
        if (nj == 0 && cntP) atomicAdd(&g_P, (unsigned)cntP);
        if (pi == 0 && cntN) atomicAdd(&g_N, (unsigned)cntN);
    }

    // ---- pair phase: 4 positives x 32 negatives per unit ---------------------
    int G4 = (cntP + 3) >> 2;                 // pos groups of 4
    if (G4 < 1) G4 = 1;
    int nCh = (cntN + 31) >> 5;               // neg chunks of 32 (8 ull2)
    const int units = G4 * nCh;               // ~258 typical

    const float4* __restrict__ posf4 =
        reinterpret_cast<const float4*>(sPos);
    const ulonglong2* __restrict__ negu =
        reinterpret_cast<const ulonglong2*>(sNeg);  // 1 ull2 = 4 negs
    const u64 S2 = pk2(0.015625f, 0.015625f); // 1/64

    float lgSum = 0.0f;
    int   nUnits = 0;
    for (int u = (int)threadIdx.x; u < units; u += TPB) {
        int chunk = u / G4;                   // consecutive threads share chunk
        int pg    = u - chunk * G4;

        float4 Fa = posf4[pg];                // 4 positives, coalesced
        u64 F0 = mul2(pk2(Fa.x, Fa.x), S2);   // lane-broadcast F/64
        u64 F1 = mul2(pk2(Fa.y, Fa.y), S2);
        u64 F2 = mul2(pk2(Fa.z, Fa.z), S2);
        u64 F3 = mul2(pk2(Fa.w, Fa.w), S2);

        const ulonglong2* qp = negu + chunk * 8;
        u64 m0, m1, m2, m3;
        {
            ulonglong2 qq = qp[0];
            m0 = mul2(fma2(qq.x, F0, S2), fma2(qq.y, F0, S2));
            m1 = mul2(fma2(qq.x, F1, S2), fma2(qq.y, F1, S2));
            m2 = mul2(fma2(qq.x, F2, S2), fma2(qq.y, F2, S2));
            m3 = mul2(fma2(qq.x, F3, S2), fma2(qq.y, F3, S2));
        }
#pragma unroll
        for (int k = 1; k < 8; ++k) {
            ulonglong2 qq = qp[k];
            m0 = mul2(m0, mul2(fma2(qq.x, F0, S2), fma2(qq.y, F0, S2)));
            m1 = mul2(m1, mul2(fma2(qq.x, F1, S2), fma2(qq.y, F1, S2)));
            m2 = mul2(m2, mul2(fma2(qq.x, F2, S2), fma2(qq.y, F2, S2)));
            m3 = mul2(m3, mul2(fma2(qq.x, F3, S2), fma2(qq.y, F3, S2)));
        }
        float a, b;
        upk2(m0, a, b); lgSum += __log2f(a) + __log2f(b);
        upk2(m1, a, b); lgSum += __log2f(a) + __log2f(b);
        upk2(m2, a, b); lgSum += __log2f(a) + __log2f(b);
        upk2(m3, a, b); lgSum += __log2f(a) + __log2f(b);
        ++nUnits;
    }
    // Each unit: 8 scalar chains of 16 t' values; +16*log2(64)=96 per chain
    // -> +768 per unit. Zero pads contribute log2(1/64) = -6 each, exactly
    // cancelled by the same correction.
    float threadSum = (lgSum + 768.0f * (float)nUnits) * 0.6931471805599453f;

    // ---- block reduction ------------------------------------------------------
#pragma unroll
    for (int off = 16; off > 0; off >>= 1)
        threadSum += __shfl_down_sync(0xFFFFFFFFu, threadSum, off);
    if (lane == 0) sRed[warp] = threadSum;
    __syncthreads();
    if (warp == 0) {
        float s = (lane < WARPS) ? sRed[lane] : 0.0f;
#pragma unroll
        for (int off = 16; off > 0; off >>= 1)
            s += __shfl_down_sync(0xFFFFFFFFu, s, off);

        // ---- slotted accumulate + last-block finalize --------------------------
        if (lane == 0) {
            atomicAdd(&g_accSlot[blockIdx.x & (NSLOT - 1)], (double)s);
            __threadfence();
            unsigned int d = atomicAdd(&g_done, 1u);
            if (d == GRID - 1) {
                __threadfence();
                double acc = 0.0;
#pragma unroll
                for (int k = 0; k < NSLOT; ++k) {
                    acc += *(volatile double*)&g_accSlot[k];
                    g_accSlot[k] = 0.0;
                }
                double P = (double)*(volatile unsigned int*)&g_P;
                double N = (double)*(volatile unsigned int*)&g_N;
                out[0] = (float)(acc / (P * N));
                g_P = 0u;
                g_N = 0u;
                g_done = 0u;
            }
        }
    }
}

// ---------------------------------------------------------------------------
extern "C" void kernel_launch(void* const* d_in, const int* in_sizes, int n_in,
                              void* d_out, int out_size) {
    const float* pred  = (const float*)d_in[0];
    const int*   label = (const int*)d_in[1];
    int total = in_sizes[0];   // n*K = 8192

    rul_tile_kernel<<<GRID, TPB>>>(pred, label, total, (float*)d_out);
}